// round 8
// baseline (speedup 1.0000x reference)
#include <cuda_runtime.h>
#include <cuda_fp16.h>
#include <cstdint>

// Fused conv3x3-VALID + bias + mish + BN(inference), implicit GEMM on
// mma.sync m16n8k16 fp16 (x and weights fp16; rel_err ~3e-4 < 1e-3).
// Per CTA: ONE (n,h) output row, 256 threads / 8 warps, 2 CTAs per SM.
// Warp tile 64 px x 32 oc. M=128 px, N=128 oc, K=9 taps x 64 ic.
// Staged prologue: A row0+B tap0 first; A rows 1/2 ride later prefetch groups.

#define HIN   128
#define WIN   128
#define CINC  64
#define COUTC 128
#define HOUTC 126
#define WOUTC 126
#define NBATCH 32

__device__ __align__(16) __half g_xh[NBATCH * HIN * WIN * CINC];  // NHWC fp16
__device__ __align__(16) __half g_bh[9 * COUTC * CINC];           // [tap][oc][ic]

__device__ __forceinline__ uint32_t smem_u32(const void* p) {
    uint32_t a;
    asm("{ .reg .u64 t; cvta.to.shared.u64 t, %1; cvt.u32.u64 %0, t; }" : "=r"(a) : "l"(p));
    return a;
}
#define SW128(o) ((o) ^ (((o) >> 3) & 0x70))

#define CP_ASYNC16(dst, src) \
    asm volatile("cp.async.cg.shared.global [%0], [%1], 16;" :: "r"(dst), "l"(src) : "memory")
#define CP_COMMIT() asm volatile("cp.async.commit_group;" ::: "memory")
#define CP_WAIT0()  asm volatile("cp.async.wait_group 0;" ::: "memory")

__device__ __forceinline__ void ldsm_x4(uint32_t addr, uint32_t* r) {
    asm volatile("ldmatrix.sync.aligned.m8n8.x4.shared.b16 {%0,%1,%2,%3}, [%4];"
        : "=r"(r[0]), "=r"(r[1]), "=r"(r[2]), "=r"(r[3]) : "r"(addr));
}
__device__ __forceinline__ void mma_fp16(float* d, const uint32_t* a,
                                         uint32_t b0, uint32_t b1) {
    asm volatile("mma.sync.aligned.m16n8k16.row.col.f32.f16.f16.f32 "
        "{%0,%1,%2,%3}, {%4,%5,%6,%7}, {%8,%9}, {%0,%1,%2,%3};"
        : "+f"(d[0]), "+f"(d[1]), "+f"(d[2]), "+f"(d[3])
        : "r"(a[0]), "r"(a[1]), "r"(a[2]), "r"(a[3]), "r"(b0), "r"(b1));
}

// ---------------- prepass: weights OIHW fp32 -> [tap][oc][ic] fp16 --------
__global__ void wprep_kernel(const float* __restrict__ wgt) {
    int i = blockIdx.x * 256 + threadIdx.x;
    if (i >= 9 * COUTC * CINC) return;
    int oc = i / (9 * CINC);
    int j  = i - oc * (9 * CINC);
    int t  = j >> 6;
    int ic = j & 63;
    g_bh[(t * COUTC + oc) * CINC + ic] = __float2half(wgt[oc * 576 + ic * 9 + t]);
}

// ---------------- prepass: x NCHW fp32 -> NHWC fp16 ----------------
__global__ void xprep_kernel(const float* __restrict__ x) {
    __shared__ float s[CINC][132];   // 132 keeps rows 16B-aligned, conflict-free
    const int h = blockIdx.x, n = blockIdx.y, tid = threadIdx.x;
    // vectorized loads: 64 ch x 32 float4 chunks
    for (int i = tid; i < CINC * 32; i += 256) {
        const int ic = i >> 5, ch = i & 31;
        const float4 v = *(const float4*)(x + ((((size_t)n * CINC) + ic) * HIN + h) * WIN + ch * 4);
        *(float4*)&s[ic][ch * 4] = v;
    }
    __syncthreads();
    const int outbase = ((n * HIN + h) * WIN) * CINC;
    for (int j = tid; j < WIN * 8; j += 256) {
        int w = j >> 3, icg = j & 7;
        __align__(16) __half h8[8];
#pragma unroll
        for (int u = 0; u < 8; u++) h8[u] = __float2half(s[icg * 8 + u][w]);
        *(uint4*)(g_xh + outbase + w * CINC + icg * 8) = *(uint4*)h8;
    }
}

// ---------------- main kernel ----------------
// smem: params(2048) | A: 3 x 16KB (input rows h..h+2) | B: 2 x 16KB dbl buf
#define SM_PAR 0
#define SM_A   2048
#define SM_B   (SM_A + 3 * 16384)
#define SMEM_TOTAL (SM_B + 2 * 16384)   // 82 KB -> 2 CTAs/SM

__device__ __forceinline__ void load_a_row(uint32_t sbase, const __half* xrow,
                                           int rowidx, int tid) {
#pragma unroll
    for (int k = 0; k < 4; k++) {
        const int idx = tid + k * 256;        // 0..1023
        const int r = idx >> 3, c = idx & 7;  // pixel w, 16B chunk
        const uint32_t dst = sbase + SM_A + rowidx * 16384 +
                             SW128((uint32_t)(r * 128 + c * 16));
        CP_ASYNC16(dst, xrow + r * CINC + c * 8);
    }
}
__device__ __forceinline__ void load_b_tap(uint32_t sbase, int tap, int buf, int tid) {
#pragma unroll
    for (int k = 0; k < 4; k++) {
        const int idx = tid + k * 256;
        const int r = idx >> 3, c = idx & 7;  // oc, chunk
        const uint32_t dst = sbase + SM_B + buf * 16384 +
                             SW128((uint32_t)(r * 128 + c * 16));
        CP_ASYNC16(dst, g_bh + (tap * COUTC + r) * CINC + c * 8);
    }
}

__global__ __launch_bounds__(256, 2)
void conv_hmma_kernel(const float* __restrict__ bias,
                      const float* __restrict__ gamma,
                      const float* __restrict__ beta,
                      const float* __restrict__ rmean,
                      const float* __restrict__ rvar,
                      float* __restrict__ out)
{
    extern __shared__ char smem[];
    const uint32_t sbase = smem_u32(smem);
    const int tid = threadIdx.x, lane = tid & 31, wid = tid >> 5;
    const int h = blockIdx.x, n = blockIdx.y;

    const __half* xrows = g_xh + ((size_t)(n * HIN + h) * WIN) * CINC;

    // group 0: A row0 + B tap0 only (32 KB) -> halved startup exposure
    load_a_row(sbase, xrows, 0, tid);
    load_b_tap(sbase, 0, 0, tid);
    CP_COMMIT();

    if (tid < COUTC) {
        const float sc = gamma[tid] * rsqrtf(rvar[tid] + 1e-5f);
        ((float*)(smem + SM_PAR))[tid]        = bias[tid];
        ((float*)(smem + SM_PAR + 512))[tid]  = sc;
        ((float*)(smem + SM_PAR + 1024))[tid] = beta[tid] - rmean[tid] * sc;
    }
    CP_WAIT0();
    __syncthreads();

    // warp tile: 64 px x 32 oc
    const int mw = (wid & 1) * 64;      // pixel base
    const int n0 = (wid >> 1) * 32;     // oc base

    float acc[4][4][4];
#pragma unroll
    for (int i = 0; i < 4; i++)
#pragma unroll
        for (int j = 0; j < 4; j++)
#pragma unroll
            for (int e = 0; e < 4; e++) acc[i][j][e] = 0.0f;

#pragma unroll
    for (int t = 0; t < 9; t++) {
        const int b = t & 1;
        // prefetch next tap's B; A rows 1/2 ride taps 0/1's commits
        if (t < 8) {
            load_b_tap(sbase, t + 1, b ^ 1, tid);
            if (t == 0) load_a_row(sbase, xrows + WIN * CINC, 1, tid);
            if (t == 1) load_a_row(sbase, xrows + 2 * WIN * CINC, 2, tid);
            CP_COMMIT();
        }

        const int kh = t / 3, kw = t - kh * 3;   // compile-time after unroll
        const uint32_t aT = sbase + SM_A + kh * 16384;
        const uint32_t bT = sbase + SM_B + b * 16384;

#pragma unroll
        for (int ks = 0; ks < 4; ks++) {
            uint32_t ah[4][4];
#pragma unroll
            for (int i = 0; i < 4; i++) {
                // row can exceed 127 for kw>0: reads spill into adjacent smem
                // and feed only discarded outputs (w>=126). Bits are finite fp16.
                const int row = mw + i * 16 + (lane & 15) + kw;
                const uint32_t off =
                    SW128((uint32_t)(row * 128 + (ks * 2 + (lane >> 4)) * 16));
                ldsm_x4(aT + off, ah[i]);
            }
#pragma unroll
            for (int jj = 0; jj < 2; jj++) {
                const int quad = lane >> 3;
                const int brow = n0 + jj * 16 + (quad >> 1) * 8 + (lane & 7);
                const uint32_t boff =
                    SW128((uint32_t)(brow * 128 + (ks * 2 + (quad & 1)) * 16));
                uint32_t bf[4];
                ldsm_x4(bT + boff, bf);
#pragma unroll
                for (int i = 0; i < 4; i++) {
                    mma_fp16(acc[i][jj * 2],     ah[i], bf[0], bf[1]);
                    mma_fp16(acc[i][jj * 2 + 1], ah[i], bf[2], bf[3]);
                }
            }
        }

        if (t < 8) CP_WAIT0();
        __syncthreads();
    }

    // --- epilogue: bias + mish + BN ---
    const float* s_bias  = (const float*)(smem + SM_PAR);
    const float* s_scale = (const float*)(smem + SM_PAR + 512);
    const float* s_shift = (const float*)(smem + SM_PAR + 1024);

#pragma unroll
    for (int i = 0; i < 4; i++)
#pragma unroll
        for (int j = 0; j < 4; j++)
#pragma unroll
            for (int e = 0; e < 4; e++) {
                const int w  = mw + i * 16 + (lane >> 2) + ((e & 2) ? 8 : 0);
                const int oc = n0 + j * 8 + (lane & 3) * 2 + (e & 1);
                if (w < WOUTC) {
                    const float z = acc[i][j][e] + s_bias[oc];
                    // mish: z*tanh(softplus(z)) = z*v/(v+2), v = e^z*(e^z+2)
                    float u;
                    asm("ex2.approx.f32 %0, %1;" : "=f"(u) : "f"(z * 1.44269504f));
                    const float v = u * (u + 2.0f);
                    float m = z * __fdividef(v, v + 2.0f);
                    if (z > 30.0f) m = z;
                    out[(((size_t)n * COUTC + oc) * HOUTC + h) * WOUTC + w] =
                        fmaf(m, s_scale[oc], s_shift[oc]);
                }
            }
}

// ---------------- launch ----------------
extern "C" void kernel_launch(void* const* d_in, const int* in_sizes, int n_in,
                              void* d_out, int out_size)
{
    const float* x     = (const float*)d_in[0];
    const float* wgt   = (const float*)d_in[1];
    const float* bias  = (const float*)d_in[2];
    const float* gamma = (const float*)d_in[3];
    const float* beta  = (const float*)d_in[4];
    const float* rmean = (const float*)d_in[5];
    const float* rvar  = (const float*)d_in[6];
    float* out = (float*)d_out;

    cudaFuncSetAttribute(conv_hmma_kernel,
                         cudaFuncAttributeMaxDynamicSharedMemorySize, SMEM_TOTAL);

    wprep_kernel<<<(9 * COUTC * CINC + 255) / 256, 256>>>(wgt);
    xprep_kernel<<<dim3(HIN, NBATCH), 256>>>(x);
    conv_hmma_kernel<<<dim3(HOUTC, NBATCH), 256, SMEM_TOTAL>>>(bias, gamma, beta,
                                                               rmean, rvar, out);
}

// round 9
// speedup vs baseline: 1.1001x; 1.1001x over previous
#include <cuda_runtime.h>
#include <cuda_fp16.h>
#include <cstdint>

// Fused conv3x3-VALID + bias + mish + BN(inference), implicit GEMM on
// mma.sync m16n8k16 fp16 (x and weights fp16; rel_err ~3e-4 < 1e-3).
// Per CTA: ONE (n,h) output row, 256 threads / 8 warps, 2 CTAs per SM.
// Warp tile 64 px x 32 oc. M=128 px, N=128 oc, K=9 taps x 64 ic.
// B triple-buffered, prefetch distance 2, wait_group 1 in the tap loop.

#define HIN   128
#define WIN   128
#define CINC  64
#define COUTC 128
#define HOUTC 126
#define WOUTC 126
#define NBATCH 32

__device__ __align__(16) __half g_xh[NBATCH * HIN * WIN * CINC];  // NHWC fp16
__device__ __align__(16) __half g_bh[9 * COUTC * CINC];           // [tap][oc][ic]

__device__ __forceinline__ uint32_t smem_u32(const void* p) {
    uint32_t a;
    asm("{ .reg .u64 t; cvta.to.shared.u64 t, %1; cvt.u32.u64 %0, t; }" : "=r"(a) : "l"(p));
    return a;
}
#define SW128(o) ((o) ^ (((o) >> 3) & 0x70))

#define CP_ASYNC16(dst, src) \
    asm volatile("cp.async.cg.shared.global [%0], [%1], 16;" :: "r"(dst), "l"(src) : "memory")
#define CP_COMMIT()  asm volatile("cp.async.commit_group;" ::: "memory")
#define CP_WAIT0()   asm volatile("cp.async.wait_group 0;" ::: "memory")
#define CP_WAIT1()   asm volatile("cp.async.wait_group 1;" ::: "memory")

__device__ __forceinline__ void ldsm_x4(uint32_t addr, uint32_t* r) {
    asm volatile("ldmatrix.sync.aligned.m8n8.x4.shared.b16 {%0,%1,%2,%3}, [%4];"
        : "=r"(r[0]), "=r"(r[1]), "=r"(r[2]), "=r"(r[3]) : "r"(addr));
}
__device__ __forceinline__ void mma_fp16(float* d, const uint32_t* a,
                                         uint32_t b0, uint32_t b1) {
    asm volatile("mma.sync.aligned.m16n8k16.row.col.f32.f16.f16.f32 "
        "{%0,%1,%2,%3}, {%4,%5,%6,%7}, {%8,%9}, {%0,%1,%2,%3};"
        : "+f"(d[0]), "+f"(d[1]), "+f"(d[2]), "+f"(d[3])
        : "r"(a[0]), "r"(a[1]), "r"(a[2]), "r"(a[3]), "r"(b0), "r"(b1));
}

// ---------------- prepass: weights OIHW fp32 -> [tap][oc][ic] fp16 --------
__global__ void wprep_kernel(const float* __restrict__ wgt) {
    int i = blockIdx.x * 256 + threadIdx.x;
    if (i >= 9 * COUTC * CINC) return;
    int oc = i / (9 * CINC);
    int j  = i - oc * (9 * CINC);
    int t  = j >> 6;
    int ic = j & 63;
    g_bh[(t * COUTC + oc) * CINC + ic] = __float2half(wgt[oc * 576 + ic * 9 + t]);
}

// ---------------- prepass: x NCHW fp32 -> NHWC fp16 ----------------
__global__ void xprep_kernel(const float* __restrict__ x) {
    __shared__ float s[CINC][132];
    const int h = blockIdx.x, n = blockIdx.y, tid = threadIdx.x;
    for (int i = tid; i < CINC * 32; i += 256) {
        const int ic = i >> 5, ch = i & 31;
        const float4 v = *(const float4*)(x + ((((size_t)n * CINC) + ic) * HIN + h) * WIN + ch * 4);
        *(float4*)&s[ic][ch * 4] = v;
    }
    __syncthreads();
    const int outbase = ((n * HIN + h) * WIN) * CINC;
    for (int j = tid; j < WIN * 8; j += 256) {
        int w = j >> 3, icg = j & 7;
        __align__(16) __half h8[8];
#pragma unroll
        for (int u = 0; u < 8; u++) h8[u] = __float2half(s[icg * 8 + u][w]);
        *(uint4*)(g_xh + outbase + w * CINC + icg * 8) = *(uint4*)h8;
    }
}

// ---------------- main kernel ----------------
// smem: params(2048) | A: 3 x 16KB (input rows h..h+2) | B: 3 x 16KB ring
#define SM_PAR 0
#define SM_A   2048
#define SM_B   (SM_A + 3 * 16384)
#define SMEM_TOTAL (SM_B + 3 * 16384)   // 98 KB -> 2 CTAs/SM

__device__ __forceinline__ void load_b_tap(uint32_t sbase, int tap, int buf, int tid) {
#pragma unroll
    for (int k = 0; k < 4; k++) {
        const int idx = tid + k * 256;
        const int r = idx >> 3, c = idx & 7;  // oc, chunk
        const uint32_t dst = sbase + SM_B + buf * 16384 +
                             SW128((uint32_t)(r * 128 + c * 16));
        CP_ASYNC16(dst, g_bh + (tap * COUTC + r) * CINC + c * 8);
    }
}

__global__ __launch_bounds__(256, 2)
void conv_hmma_kernel(const float* __restrict__ bias,
                      const float* __restrict__ gamma,
                      const float* __restrict__ beta,
                      const float* __restrict__ rmean,
                      const float* __restrict__ rvar,
                      float* __restrict__ out)
{
    extern __shared__ char smem[];
    const uint32_t sbase = smem_u32(smem);
    const int tid = threadIdx.x, lane = tid & 31, wid = tid >> 5;
    const int h = blockIdx.x, n = blockIdx.y;

    if (tid < COUTC) {
        const float sc = gamma[tid] * rsqrtf(rvar[tid] + 1e-5f);
        ((float*)(smem + SM_PAR))[tid]        = bias[tid];
        ((float*)(smem + SM_PAR + 512))[tid]  = sc;
        ((float*)(smem + SM_PAR + 1024))[tid] = beta[tid] - rmean[tid] * sc;
    }

    // --- group G0: A rows h..h+2 + B tap0 (front-batched for MLP) ---
#pragma unroll
    for (int k = 0; k < 12; k++) {
        const int idx  = tid + k * 256;       // 0..3071
        const int tile = idx >> 10;           // input row 0..2
        const int wit  = idx & 1023;
        const int r = wit >> 3, c = wit & 7;  // pixel w, 16B chunk
        const __half* src = g_xh + (((n * HIN + (h + tile)) * WIN) + r) * CINC + c * 8;
        const uint32_t dst = sbase + SM_A + tile * 16384 +
                             SW128((uint32_t)(r * 128 + c * 16));
        CP_ASYNC16(dst, src);
    }
    load_b_tap(sbase, 0, 0, tid);
    CP_COMMIT();
    // --- group G1: B tap1 ---
    load_b_tap(sbase, 1, 1, tid);
    CP_COMMIT();

    CP_WAIT1();           // G0 (A + B0) complete; B1 may still be in flight
    __syncthreads();

    // warp tile: 64 px x 32 oc
    const int mw = (wid & 1) * 64;      // pixel base
    const int n0 = (wid >> 1) * 32;     // oc base

    float acc[4][4][4];
#pragma unroll
    for (int i = 0; i < 4; i++)
#pragma unroll
        for (int j = 0; j < 4; j++)
#pragma unroll
            for (int e = 0; e < 4; e++) acc[i][j][e] = 0.0f;

    for (int t = 0; t < 9; t++) {
        const int b = t - (t / 3) * 3 + ((t / 3) & 1) * (3 - 2 * (t - (t / 3) * 3));
        // simpler: buf index = t % 3
        const int buf = t % 3;
        (void)b;
        if (t < 7) {   // prefetch tap t+2 into ring slot (t+2)%3
            load_b_tap(sbase, t + 2, (t + 2) % 3, tid);
            CP_COMMIT();
        }

        const int kh = t / 3, kw = t - kh * 3;
        const uint32_t aT = sbase + SM_A + kh * 16384;
        const uint32_t bT = sbase + SM_B + buf * 16384;

#pragma unroll
        for (int ks = 0; ks < 4; ks++) {
            uint32_t ah[4][4];
#pragma unroll
            for (int i = 0; i < 4; i++) {
                // row can exceed 127 for kw>0: reads spill into adjacent smem
                // and feed only discarded outputs (w>=126). Bits are finite fp16.
                const int row = mw + i * 16 + (lane & 15) + kw;
                const uint32_t off =
                    SW128((uint32_t)(row * 128 + (ks * 2 + (lane >> 4)) * 16));
                ldsm_x4(aT + off, ah[i]);
            }
#pragma unroll
            for (int jj = 0; jj < 2; jj++) {
                const int quad = lane >> 3;
                const int brow = n0 + jj * 16 + (quad >> 1) * 8 + (lane & 7);
                const uint32_t boff =
                    SW128((uint32_t)(brow * 128 + (ks * 2 + (quad & 1)) * 16));
                uint32_t bf[4];
                ldsm_x4(bT + boff, bf);
#pragma unroll
                for (int i = 0; i < 4; i++) {
                    mma_fp16(acc[i][jj * 2],     ah[i], bf[0], bf[1]);
                    mma_fp16(acc[i][jj * 2 + 1], ah[i], bf[2], bf[3]);
                }
            }
        }

        // ensure B(t+1) complete before the barrier; B(t+2) may stay in flight
        if (t < 7)      CP_WAIT1();
        else if (t == 7) CP_WAIT0();
        if (t < 8) __syncthreads();
    }

    // --- epilogue: bias + mish + BN ---
    const float* s_bias  = (const float*)(smem + SM_PAR);
    const float* s_scale = (const float*)(smem + SM_PAR + 512);
    const float* s_shift = (const float*)(smem + SM_PAR + 1024);

#pragma unroll
    for (int i = 0; i < 4; i++)
#pragma unroll
        for (int j = 0; j < 4; j++)
#pragma unroll
            for (int e = 0; e < 4; e++) {
                const int w  = mw + i * 16 + (lane >> 2) + ((e & 2) ? 8 : 0);
                const int oc = n0 + j * 8 + (lane & 3) * 2 + (e & 1);
                if (w < WOUTC) {
                    const float z = acc[i][j][e] + s_bias[oc];
                    // mish: z*tanh(softplus(z)) = z*v/(v+2), v = e^z*(e^z+2)
                    float u;
                    asm("ex2.approx.f32 %0, %1;" : "=f"(u) : "f"(z * 1.44269504f));
                    const float v = u * (u + 2.0f);
                    float m = z * __fdividef(v, v + 2.0f);
                    if (z > 30.0f) m = z;
                    out[(((size_t)n * COUTC + oc) * HOUTC + h) * WOUTC + w] =
                        fmaf(m, s_scale[oc], s_shift[oc]);
                }
            }
}

// ---------------- launch ----------------
extern "C" void kernel_launch(void* const* d_in, const int* in_sizes, int n_in,
                              void* d_out, int out_size)
{
    const float* x     = (const float*)d_in[0];
    const float* wgt   = (const float*)d_in[1];
    const float* bias  = (const float*)d_in[2];
    const float* gamma = (const float*)d_in[3];
    const float* beta  = (const float*)d_in[4];
    const float* rmean = (const float*)d_in[5];
    const float* rvar  = (const float*)d_in[6];
    float* out = (float*)d_out;

    cudaFuncSetAttribute(conv_hmma_kernel,
                         cudaFuncAttributeMaxDynamicSharedMemorySize, SMEM_TOTAL);

    wprep_kernel<<<(9 * COUTC * CINC + 255) / 256, 256>>>(wgt);
    xprep_kernel<<<dim3(HIN, NBATCH), 256>>>(x);
    conv_hmma_kernel<<<dim3(HOUTC, NBATCH), 256, SMEM_TOTAL>>>(bias, gamma, beta,
                                                               rmean, rvar, out);
}